// round 5
// baseline (speedup 1.0000x reference)
#include <cuda_runtime.h>
#include <cuda_bf16.h>
#include <cstdint>

// ---------------------------------------------------------------------------
// Persistent fused teacher-attention KD kernel (BN=16 nodes per tile).
//   t_proj[t,n,h] = t_out[t,n,:] @ W1^T + b1 ; s_proj = s_out @ W2^T + b2
//   kl[t,n] = sum_h softmax(t_proj)*(log_softmax(t_proj) - log_softmax(s_proj))
//   w[t,n]  = softmax_t(-kl/sqrt(128)) ; out[n,:] = sum_t w[t,n]*t_out[t,n,:]
//
// grid = #SMs (persistent, grid-stride over 6250 tiles). Weights live in
// registers (loaded once per CTA). Input tiles double-buffered in smem via
// one cp.async group per tile -> no wave transitions, no per-CTA weight
// re-reads. kl values round-trip through a tiny per-lane smem strip (dynamic
// index in a non-unrolled loop would otherwise spill to local memory).
// Paper model: ~1150 cyc HMMA + ~1150 cyc MUFU per tile (overlapping pipes),
// chip feed ~4.5 KB/cyc < 6.3 KB/cyc LTS cap -> 1-deep lookahead suffices.
// ---------------------------------------------------------------------------

namespace {

constexpr int T_MODELS = 8;
constexpr int N_NODES  = 100000;
constexpr int C_IN     = 128;
constexpr int BN       = 16;                  // nodes per tile
constexpr int NTILES   = N_NODES / BN;        // 6250
constexpr int NTHREADS = 256;                 // 8 warps; warp q owns 16 output cols
constexpr int XSTR     = 136;                 // padded row stride (floats)
constexpr int SUBT     = BN * XSTR;           // 2176 floats per sub-tile
constexpr int BUFT     = 9 * SUBT;            // 19584 floats per tile set

// dynamic smem layout (bytes)
constexpr int OFF_RED     = 2 * BUFT * 4;                  // float2 red[2][16][8] = 2048 B
constexpr int OFF_LSE     = OFF_RED + 2 * 16 * 8 * 8;      // fp32[16]
constexpr int OFF_KL      = OFF_LSE + 64;                  // fp32[8][16]
constexpr int OFF_WT      = OFF_KL + 512;                  // fp32[8][16]
constexpr int SMEM_TOTAL  = OFF_WT + 512;                  // 159808 B

__device__ __forceinline__ uint32_t pack_bf16x2(float lo, float hi) {
    __nv_bfloat162 b = __floats2bfloat162_rn(lo, hi);
    return *reinterpret_cast<uint32_t*>(&b);
}

__device__ __forceinline__ void mma16816(float c[4], const uint32_t a[4], uint32_t b0, uint32_t b1) {
    asm volatile(
        "mma.sync.aligned.m16n8k16.row.col.f32.bf16.bf16.f32 "
        "{%0,%1,%2,%3},{%4,%5,%6,%7},{%8,%9},{%0,%1,%2,%3};\n"
        : "+f"(c[0]), "+f"(c[1]), "+f"(c[2]), "+f"(c[3])
        : "r"(a[0]), "r"(a[1]), "r"(a[2]), "r"(a[3]), "r"(b0), "r"(b1));
}

__device__ __forceinline__ void cp16(void* dst, const void* src) {
    uint32_t d = (uint32_t)__cvta_generic_to_shared(dst);
    asm volatile("cp.async.cg.shared.global [%0], [%1], 16;\n" :: "r"(d), "l"(src) : "memory");
}

// Build this thread's A fragments for k-step kk from an fp32 smem tile (rows g, g+8).
// Bank analysis (4B banks, LDS.64 in two 16-lane phases): addr/4 = g*136 + kk*16
// + tc*2 (+8); g*8 + tc*2 covers distinct even banks, +1 odd -> conflict-free.
__device__ __forceinline__ void build_a(const float* __restrict__ xt,
                                        int g, int tc, int kk, uint32_t a[4]) {
    const int cb = kk * 16 + tc * 2;
    float2 v;
    v = *reinterpret_cast<const float2*>(xt + (g)     * XSTR + cb);     a[0] = pack_bf16x2(v.x, v.y);
    v = *reinterpret_cast<const float2*>(xt + (g + 8) * XSTR + cb);     a[1] = pack_bf16x2(v.x, v.y);
    v = *reinterpret_cast<const float2*>(xt + (g)     * XSTR + cb + 8); a[2] = pack_bf16x2(v.x, v.y);
    v = *reinterpret_cast<const float2*>(xt + (g + 8) * XSTR + cb + 8); a[3] = pack_bf16x2(v.x, v.y);
}

} // namespace

__global__ void __launch_bounds__(NTHREADS, 1)
fused_kd_attn(const float* __restrict__ s_out, const float* __restrict__ t_out,
              const float* __restrict__ w1w, const float* __restrict__ w1b,
              const float* __restrict__ w2w, const float* __restrict__ w2b,
              float* __restrict__ out) {
    extern __shared__ char smraw[];
    float*  xs    = reinterpret_cast<float*>(smraw);                 // [2][9][16][136]
    float2* redsh = reinterpret_cast<float2*>(smraw + OFF_RED);      // [2][16][8]
    float*  lsesh = reinterpret_cast<float*>(smraw + OFF_LSE);       // [16]
    float*  klsh  = reinterpret_cast<float*>(smraw + OFF_KL);        // [8][16]
    float*  wtsh  = reinterpret_cast<float*>(smraw + OFF_WT);        // [8][16]

    const int tid  = threadIdx.x;
    const int lane = tid & 31;
    const int q    = tid >> 5;    // warp: cols [16q, 16q+16)
    const int g    = lane >> 2;   // 0..7
    const int tc   = lane & 3;    // 0..3

    // ---- weights + biases -> registers (once per CTA) -----------------------
    uint32_t wf1[2][8][2], wf2[2][8][2];
    float2 b1r[2], b2r[2];
#pragma unroll
    for (int nt = 0; nt < 2; nt++) {
        const int col = q * 16 + nt * 8 + g;        // B-fragment n index = g
#pragma unroll
        for (int kk = 0; kk < 8; kk++) {
            const int kb = kk * 16 + tc * 2;
            float2 v;
            v = *reinterpret_cast<const float2*>(w1w + col * C_IN + kb);     wf1[nt][kk][0] = pack_bf16x2(v.x, v.y);
            v = *reinterpret_cast<const float2*>(w1w + col * C_IN + kb + 8); wf1[nt][kk][1] = pack_bf16x2(v.x, v.y);
            v = *reinterpret_cast<const float2*>(w2w + col * C_IN + kb);     wf2[nt][kk][0] = pack_bf16x2(v.x, v.y);
            v = *reinterpret_cast<const float2*>(w2w + col * C_IN + kb + 8); wf2[nt][kk][1] = pack_bf16x2(v.x, v.y);
        }
        const int bc = q * 16 + nt * 8 + tc * 2;    // C-fragment n index = tc*2
        b1r[nt] = *reinterpret_cast<const float2*>(w1b + bc);
        b2r[nt] = *reinterpret_cast<const float2*>(w2b + bc);
    }

    // ---- persistent grid-stride loop with double-buffered cp.async ----------
    int cur = blockIdx.x;
    int p = 0;
    // prologue: issue loads for first tile into buffer 0 (one commit group = 9 sub-tiles)
    if (cur < NTILES) {
        const long node0 = (long)cur * BN;
#pragma unroll
        for (int i = 0; i < 2; i++) {
            const int id = tid + i * 256;
            const int r = id >> 5, c4 = id & 31;
            cp16(xs + 8 * SUBT + r * XSTR + c4 * 4, s_out + (node0 + r) * C_IN + c4 * 4);
        }
#pragma unroll
        for (int t = 0; t < T_MODELS; t++)
#pragma unroll
            for (int i = 0; i < 2; i++) {
                const int id = tid + i * 256;
                const int r = id >> 5, c4 = id & 31;
                cp16(xs + t * SUBT + r * XSTR + c4 * 4,
                     t_out + ((long)t * N_NODES + node0 + r) * C_IN + c4 * 4);
            }
        asm volatile("cp.async.commit_group;\n" ::: "memory");
    }

#pragma unroll 1
    while (cur < NTILES) {
        __syncthreads();   // (A) all threads done reading buf[1-p] from prev iteration

        const int nxt = cur + gridDim.x;
        if (nxt < NTILES) {   // prefetch next tile into the other buffer
            float* nb = xs + (1 - p) * BUFT;
            const long nn0 = (long)nxt * BN;
#pragma unroll
            for (int i = 0; i < 2; i++) {
                const int id = tid + i * 256;
                const int r = id >> 5, c4 = id & 31;
                cp16(nb + 8 * SUBT + r * XSTR + c4 * 4, s_out + (nn0 + r) * C_IN + c4 * 4);
            }
#pragma unroll
            for (int t = 0; t < T_MODELS; t++)
#pragma unroll
                for (int i = 0; i < 2; i++) {
                    const int id = tid + i * 256;
                    const int r = id >> 5, c4 = id & 31;
                    cp16(nb + t * SUBT + r * XSTR + c4 * 4,
                         t_out + ((long)t * N_NODES + nn0 + r) * C_IN + c4 * 4);
                }
            asm volatile("cp.async.commit_group;\n" ::: "memory");
            asm volatile("cp.async.wait_group 1;\n" ::: "memory");   // current tile landed
        } else {
            asm volatile("cp.async.wait_group 0;\n" ::: "memory");
        }
        __syncthreads();   // (B) current buffer visible to all threads

        const float* buf = xs + p * BUFT;
        const long node0 = (long)cur * BN;

        // ---------------- student projection ---------------------------------
        float acc[2][4];
#pragma unroll
        for (int nt = 0; nt < 2; nt++)
#pragma unroll
            for (int k = 0; k < 4; k++) acc[nt][k] = 0.f;
#pragma unroll
        for (int kk = 0; kk < 8; kk++) {
            uint32_t a[4];
            build_a(buf + 8 * SUBT, g, tc, kk, a);
#pragma unroll
            for (int nt = 0; nt < 2; nt++)
                mma16816(acc[nt], a, wf2[nt][kk][0], wf2[nt][kk][1]);
        }
        {
            float a1p0 = 0.f, a1p1 = 0.f;
#pragma unroll
            for (int nt = 0; nt < 2; nt++) {
                acc[nt][0] += b2r[nt].x; acc[nt][1] += b2r[nt].y;
                acc[nt][2] += b2r[nt].x; acc[nt][3] += b2r[nt].y;
                a1p0 += __expf(acc[nt][0]) + __expf(acc[nt][1]);
                a1p1 += __expf(acc[nt][2]) + __expf(acc[nt][3]);
            }
            a1p0 += __shfl_xor_sync(0xffffffffu, a1p0, 1);
            a1p0 += __shfl_xor_sync(0xffffffffu, a1p0, 2);
            a1p1 += __shfl_xor_sync(0xffffffffu, a1p1, 1);
            a1p1 += __shfl_xor_sync(0xffffffffu, a1p1, 2);
            if (tc == 0) {
                redsh[(g)     * 8 + q] = make_float2(a1p0, 0.f);   // parity-0 slab
                redsh[(g + 8) * 8 + q] = make_float2(a1p1, 0.f);
            }
        }
        __syncthreads();   // (S1)
        if (tid < 16) {
            float a1 = 0.f;
#pragma unroll
            for (int qq = 0; qq < 8; qq++) a1 += redsh[tid * 8 + qq].x;
            lsesh[tid] = __logf(a1);     // logits small (|l|<~5): no max-shift needed
        }
        __syncthreads();   // (S2)

        float2 ls0[2], ls1[2];   // log-softmax(s): thread-local (same (row,col) ownership)
        {
            const float lse0 = lsesh[g];
            const float lse1 = lsesh[g + 8];
#pragma unroll
            for (int nt = 0; nt < 2; nt++) {
                ls0[nt] = make_float2(acc[nt][0] - lse0, acc[nt][1] - lse0);
                ls1[nt] = make_float2(acc[nt][2] - lse1, acc[nt][3] - lse1);
            }
        }

        // ---------------- teacher loop ---------------------------------------
#pragma unroll 1
        for (int t = 0; t < T_MODELS; t++) {
            float tacc[2][4];
#pragma unroll
            for (int nt = 0; nt < 2; nt++)
#pragma unroll
                for (int k = 0; k < 4; k++) tacc[nt][k] = 0.f;
            const float* xt = buf + t * SUBT;
#pragma unroll
            for (int kk = 0; kk < 8; kk++) {
                uint32_t a[4];
                build_a(xt, g, tc, kk, a);
#pragma unroll
                for (int nt = 0; nt < 2; nt++)
                    mma16816(tacc[nt], a, wf1[nt][kk][0], wf1[nt][kk][1]);
            }
            float a1p0 = 0.f, a1p1 = 0.f, a2p0 = 0.f, a2p1 = 0.f;
#pragma unroll
            for (int nt = 0; nt < 2; nt++) {
                float v00 = tacc[nt][0] + b1r[nt].x, v01 = tacc[nt][1] + b1r[nt].y;
                float v10 = tacc[nt][2] + b1r[nt].x, v11 = tacc[nt][3] + b1r[nt].y;
                float e00 = __expf(v00), e01 = __expf(v01);
                float e10 = __expf(v10), e11 = __expf(v11);
                a1p0 += e00 + e01;  a1p1 += e10 + e11;
                a2p0 += e00 * (v00 - ls0[nt].x) + e01 * (v01 - ls0[nt].y);
                a2p1 += e10 * (v10 - ls1[nt].x) + e11 * (v11 - ls1[nt].y);
            }
            a1p0 += __shfl_xor_sync(0xffffffffu, a1p0, 1);
            a1p0 += __shfl_xor_sync(0xffffffffu, a1p0, 2);
            a1p1 += __shfl_xor_sync(0xffffffffu, a1p1, 1);
            a1p1 += __shfl_xor_sync(0xffffffffu, a1p1, 2);
            a2p0 += __shfl_xor_sync(0xffffffffu, a2p0, 1);
            a2p0 += __shfl_xor_sync(0xffffffffu, a2p0, 2);
            a2p1 += __shfl_xor_sync(0xffffffffu, a2p1, 1);
            a2p1 += __shfl_xor_sync(0xffffffffu, a2p1, 2);
            float2* rp = redsh + (t & 1) * 16 * 8;   // parity slab: write t+2 vs read t fenced by T(t+1)
            if (tc == 0) {
                rp[(g)     * 8 + q] = make_float2(a1p0, a2p0);
                rp[(g + 8) * 8 + q] = make_float2(a1p1, a2p1);
            }
            __syncthreads();   // (T_t)
            if (tid < 16) {
                const float2* rr = redsh + (t & 1) * 16 * 8 + tid * 8;
                float a1 = 0.f, a2 = 0.f;
#pragma unroll
                for (int qq = 0; qq < 8; qq++) { float2 v = rr[qq]; a1 += v.x; a2 += v.y; }
                // per-lane smem strip (NOT a register array: dynamic t in a
                // non-unrolled loop would force a local-memory spill)
                klsh[t * 16 + tid] = a2 / a1 - __logf(a1);
            }
        }

        // ---------------- teacher softmax + combine --------------------------
        // (same lanes wrote klsh; same-thread smem st->ld needs no barrier)
        if (tid < 16) {
            const float sc = -0.08838834764831845f;   // -1/sqrt(128)
            float s[8]; float mx = -1e30f;
#pragma unroll
            for (int t = 0; t < 8; t++) { s[t] = klsh[t * 16 + tid] * sc; mx = fmaxf(mx, s[t]); }
            float sum = 0.f;
#pragma unroll
            for (int t = 0; t < 8; t++) { s[t] = __expf(s[t] - mx); sum += s[t]; }
            const float inv = 1.f / sum;
#pragma unroll
            for (int t = 0; t < 8; t++) wtsh[t * 16 + tid] = s[t] * inv;
        }
        __syncthreads();   // (W)

        {
            const int r = tid >> 4;                 // 0..15
            const int cbase = (tid & 15) * 8;       // 8 cols per thread
            float w[8];
#pragma unroll
            for (int t = 0; t < 8; t++) w[t] = wtsh[t * 16 + r];
            float* orow = out + (node0 + r) * C_IN + cbase;
#pragma unroll
            for (int j = 0; j < 2; j++) {
                float4 a4 = make_float4(0.f, 0.f, 0.f, 0.f);
#pragma unroll
                for (int t = 0; t < 8; t++) {
                    float4 xv = *reinterpret_cast<const float4*>(buf + t * SUBT + r * XSTR + cbase + j * 4);
                    a4.x += w[t] * xv.x; a4.y += w[t] * xv.y;
                    a4.z += w[t] * xv.z; a4.w += w[t] * xv.w;
                }
                *reinterpret_cast<float4*>(orow + j * 4) = a4;
            }
        }

        cur = nxt;
        p ^= 1;
    }
}

extern "C" void kernel_launch(void* const* d_in, const int* in_sizes, int n_in,
                              void* d_out, int out_size) {
    (void)in_sizes; (void)n_in; (void)out_size;
    const float* s_out = (const float*)d_in[0];
    const float* t_out = (const float*)d_in[1];
    const float* w1w   = (const float*)d_in[2];
    const float* w1b   = (const float*)d_in[3];
    const float* w2w   = (const float*)d_in[4];
    const float* w2b   = (const float*)d_in[5];
    float* out = (float*)d_out;

    int dev = 0, nsm = 0;
    cudaGetDevice(&dev);
    cudaDeviceGetAttribute(&nsm, cudaDevAttrMultiProcessorCount, dev);
    if (nsm <= 0) nsm = 148;

    cudaFuncSetAttribute(fused_kd_attn, cudaFuncAttributeMaxDynamicSharedMemorySize, SMEM_TOTAL);
    fused_kd_attn<<<nsm, NTHREADS, SMEM_TOTAL>>>(s_out, t_out, w1w, w1b, w2w, w2b, out);
}

// round 16
// speedup vs baseline: 1.0279x; 1.0279x over previous
#include <cuda_runtime.h>
#include <cuda_bf16.h>
#include <cstdint>

// ---------------------------------------------------------------------------
// Persistent fused teacher-attention KD kernel (BN=16 nodes per tile).
//   t_proj[t,n,h] = t_out[t,n,:] @ W1^T + b1 ; s_proj = s_out @ W2^T + b2
//   kl[t,n] = sum_h softmax(t_proj)*(log_softmax(t_proj) - log_softmax(s_proj))
//   w[t,n]  = softmax_t(-kl/sqrt(128)) ; out[n,:] = sum_t w[t,n]*t_out[t,n,:]
//
// grid = #SMs (persistent). Weights in registers. Tiles double-buffered fp32
// via cp.async; each tile converted ONCE to a bf16 smem copy; GEMM A
// fragments via ldmatrix.x4. Smem-crossbar model (the R5-measured bottleneck):
// LDSM 2304 + convert 918 + cpSTS 576 + combine 512 ~= 4300 cyc/tile vs 5700
// for the per-warp LDS.64+F2FP A-build this replaces (257us measured).
// ---------------------------------------------------------------------------

namespace {

constexpr int T_MODELS = 8;
constexpr int N_NODES  = 100000;
constexpr int C_IN     = 128;
constexpr int BN       = 16;                  // nodes per tile
constexpr int NTILES   = N_NODES / BN;        // 6250
constexpr int NTHREADS = 256;                 // 8 warps; warp q owns 16 output cols
constexpr int XSTR     = 136;                 // fp32 row stride (floats)
constexpr int SUBT     = BN * XSTR;           // 2176 floats per fp32 sub-tile
constexpr int BUFT     = 9 * SUBT;            // floats per fp32 tile set
constexpr int XB       = 136;                 // bf16 row stride (elems) -> 272 B
constexpr int SUBTB    = BN * XB;             // 2176 bf16 per tile = 4352 B

// dynamic smem layout (bytes)
constexpr int OFF_BF      = 2 * BUFT * 4;                  // 156672 : bf16 tiles [9][16][136]
constexpr int OFF_RED     = OFF_BF + 9 * SUBTB * 2;        // 195840 : float2 red[2][16][8]
constexpr int OFF_LSE     = OFF_RED + 2 * 16 * 8 * 8;      // fp32[16]
constexpr int OFF_KL      = OFF_LSE + 64;                  // fp32[8][16]
constexpr int OFF_WT      = OFF_KL + 512;                  // fp32[8][16]
constexpr int SMEM_TOTAL  = OFF_WT + 512;                  // 198976 B

__device__ __forceinline__ uint32_t pack_bf16x2(float lo, float hi) {
    __nv_bfloat162 b = __floats2bfloat162_rn(lo, hi);
    return *reinterpret_cast<uint32_t*>(&b);
}

__device__ __forceinline__ void mma16816(float c[4], const uint32_t a[4], uint32_t b0, uint32_t b1) {
    asm volatile(
        "mma.sync.aligned.m16n8k16.row.col.f32.bf16.bf16.f32 "
        "{%0,%1,%2,%3},{%4,%5,%6,%7},{%8,%9},{%0,%1,%2,%3};\n"
        : "+f"(c[0]), "+f"(c[1]), "+f"(c[2]), "+f"(c[3])
        : "r"(a[0]), "r"(a[1]), "r"(a[2]), "r"(a[3]), "r"(b0), "r"(b1));
}

__device__ __forceinline__ void ldsm4(uint32_t a[4], uint32_t saddr) {
    asm volatile("ldmatrix.sync.aligned.m8n8.x4.shared.b16 {%0,%1,%2,%3}, [%4];\n"
                 : "=r"(a[0]), "=r"(a[1]), "=r"(a[2]), "=r"(a[3]) : "r"(saddr));
}

__device__ __forceinline__ void cp16(void* dst, const void* src) {
    uint32_t d = (uint32_t)__cvta_generic_to_shared(dst);
    asm volatile("cp.async.cg.shared.global [%0], [%1], 16;\n" :: "r"(d), "l"(src) : "memory");
}

} // namespace

__global__ void __launch_bounds__(NTHREADS, 1)
fused_kd_attn(const float* __restrict__ s_out, const float* __restrict__ t_out,
              const float* __restrict__ w1w, const float* __restrict__ w1b,
              const float* __restrict__ w2w, const float* __restrict__ w2b,
              float* __restrict__ out) {
    extern __shared__ char smraw[];
    float*  xs    = reinterpret_cast<float*>(smraw);                 // [2][9][16][136] fp32
    char*   bfraw = smraw + OFF_BF;                                  // [9][16][136] bf16
    float2* redsh = reinterpret_cast<float2*>(smraw + OFF_RED);      // [2][16][8]
    float*  lsesh = reinterpret_cast<float*>(smraw + OFF_LSE);       // [16]
    float*  klsh  = reinterpret_cast<float*>(smraw + OFF_KL);        // [8][16]
    float*  wtsh  = reinterpret_cast<float*>(smraw + OFF_WT);        // [8][16]

    const int tid  = threadIdx.x;
    const int lane = tid & 31;
    const int q    = tid >> 5;    // warp: cols [16q, 16q+16)
    const int g    = lane >> 2;   // 0..7
    const int tc   = lane & 3;    // 0..3

    // ldmatrix.x4 per-lane address map (matches HW-validated R5 fragment
    // layout): lanes 0-7 -> A[0:8][0:8] | 8-15 -> A[8:16][0:8] |
    // 16-23 -> A[0:8][8:16] | 24-31 -> A[8:16][8:16]. Lane (g,tc) receives
    // r0=A[g][2tc..], r1=A[g+8][2tc..], r2=A[g][8+2tc..], r3=A[g+8][8+2tc..].
    const int rowsel = (lane & 7) + ((lane >> 3) & 1) * 8;
    const uint32_t lmoff = (uint32_t)(rowsel * (XB * 2) + (lane >> 4) * 16);
    const uint32_t bf_u32 = (uint32_t)__cvta_generic_to_shared(bfraw) + lmoff;

    // ---- weights + biases -> registers (once per CTA) -----------------------
    uint32_t wf1[2][8][2], wf2[2][8][2];
    float2 b1r[2], b2r[2];
#pragma unroll
    for (int nt = 0; nt < 2; nt++) {
        const int col = q * 16 + nt * 8 + g;        // B-fragment n index = g
#pragma unroll
        for (int kk = 0; kk < 8; kk++) {
            const int kb = kk * 16 + tc * 2;
            float2 v;
            v = *reinterpret_cast<const float2*>(w1w + col * C_IN + kb);     wf1[nt][kk][0] = pack_bf16x2(v.x, v.y);
            v = *reinterpret_cast<const float2*>(w1w + col * C_IN + kb + 8); wf1[nt][kk][1] = pack_bf16x2(v.x, v.y);
            v = *reinterpret_cast<const float2*>(w2w + col * C_IN + kb);     wf2[nt][kk][0] = pack_bf16x2(v.x, v.y);
            v = *reinterpret_cast<const float2*>(w2w + col * C_IN + kb + 8); wf2[nt][kk][1] = pack_bf16x2(v.x, v.y);
        }
        const int bc = q * 16 + nt * 8 + tc * 2;    // C-fragment n index = tc*2
        b1r[nt] = *reinterpret_cast<const float2*>(w1b + bc);
        b2r[nt] = *reinterpret_cast<const float2*>(w2b + bc);
    }

    // ---- persistent grid-stride loop with double-buffered cp.async ----------
    int cur = blockIdx.x;
    int p = 0;
    if (cur < NTILES) {   // prologue: first tile into buffer 0 (one commit group)
        const long node0 = (long)cur * BN;
#pragma unroll
        for (int i = 0; i < 2; i++) {
            const int id = tid + i * 256;
            const int r = id >> 5, c4 = id & 31;
            cp16(xs + 8 * SUBT + r * XSTR + c4 * 4, s_out + (node0 + r) * C_IN + c4 * 4);
        }
#pragma unroll
        for (int t = 0; t < T_MODELS; t++)
#pragma unroll
            for (int i = 0; i < 2; i++) {
                const int id = tid + i * 256;
                const int r = id >> 5, c4 = id & 31;
                cp16(xs + t * SUBT + r * XSTR + c4 * 4,
                     t_out + ((long)t * N_NODES + node0 + r) * C_IN + c4 * 4);
            }
        asm volatile("cp.async.commit_group;\n" ::: "memory");
    }

#pragma unroll 1
    while (cur < NTILES) {
        __syncthreads();   // (A) prev iteration fully consumed both smem regions

        const int nxt = cur + gridDim.x;
        if (nxt < NTILES) {   // prefetch next tile into the other fp32 buffer
            float* nb = xs + (1 - p) * BUFT;
            const long nn0 = (long)nxt * BN;
#pragma unroll
            for (int i = 0; i < 2; i++) {
                const int id = tid + i * 256;
                const int r = id >> 5, c4 = id & 31;
                cp16(nb + 8 * SUBT + r * XSTR + c4 * 4, s_out + (nn0 + r) * C_IN + c4 * 4);
            }
#pragma unroll
            for (int t = 0; t < T_MODELS; t++)
#pragma unroll
                for (int i = 0; i < 2; i++) {
                    const int id = tid + i * 256;
                    const int r = id >> 5, c4 = id & 31;
                    cp16(nb + t * SUBT + r * XSTR + c4 * 4,
                         t_out + ((long)t * N_NODES + nn0 + r) * C_IN + c4 * 4);
                }
            asm volatile("cp.async.commit_group;\n" ::: "memory");
            asm volatile("cp.async.wait_group 1;\n" ::: "memory");   // current tile landed
        } else {
            asm volatile("cp.async.wait_group 0;\n" ::: "memory");
        }
        __syncthreads();   // (B) current fp32 buffer visible

        const float* buf = xs + p * BUFT;
        const long node0 = (long)cur * BN;

        // ---- one-shot fp32 -> bf16 tile conversion (shared by all warps) ----
        // 2304 chunks of 8 elems; bfraw WAR vs prev-iter GEMM reads fenced by (T_7)+(A).
#pragma unroll
        for (int i = 0; i < 9; i++) {
            const int id = tid + i * 256;
            const int tile = id >> 8;
            const int r = (id >> 4) & 15;
            const int c8 = id & 15;
            const float* src = buf + tile * SUBT + r * XSTR + c8 * 8;
            const float4 v0 = *reinterpret_cast<const float4*>(src);
            const float4 v1 = *reinterpret_cast<const float4*>(src + 4);
            uint4 o;
            o.x = pack_bf16x2(v0.x, v0.y);  o.y = pack_bf16x2(v0.z, v0.w);
            o.z = pack_bf16x2(v1.x, v1.y);  o.w = pack_bf16x2(v1.z, v1.w);
            *reinterpret_cast<uint4*>(bfraw + tile * (SUBTB * 2) + r * (XB * 2) + c8 * 16) = o;
        }
        __syncthreads();   // (C) bf16 tiles ready

        // ---------------- student projection (bf16 tile 8) --------------------
        float acc[2][4];
#pragma unroll
        for (int nt = 0; nt < 2; nt++)
#pragma unroll
            for (int k = 0; k < 4; k++) acc[nt][k] = 0.f;
        {
            const uint32_t abase = bf_u32 + 8u * (SUBTB * 2);
#pragma unroll
            for (int kk = 0; kk < 8; kk++) {
                uint32_t a[4];
                ldsm4(a, abase + kk * 32);
#pragma unroll
                for (int nt = 0; nt < 2; nt++)
                    mma16816(acc[nt], a, wf2[nt][kk][0], wf2[nt][kk][1]);
            }
        }
        {
            float a1p0 = 0.f, a1p1 = 0.f;
#pragma unroll
            for (int nt = 0; nt < 2; nt++) {
                acc[nt][0] += b2r[nt].x; acc[nt][1] += b2r[nt].y;
                acc[nt][2] += b2r[nt].x; acc[nt][3] += b2r[nt].y;
                a1p0 += __expf(acc[nt][0]) + __expf(acc[nt][1]);
                a1p1 += __expf(acc[nt][2]) + __expf(acc[nt][3]);
            }
            a1p0 += __shfl_xor_sync(0xffffffffu, a1p0, 1);
            a1p0 += __shfl_xor_sync(0xffffffffu, a1p0, 2);
            a1p1 += __shfl_xor_sync(0xffffffffu, a1p1, 1);
            a1p1 += __shfl_xor_sync(0xffffffffu, a1p1, 2);
            if (tc == 0) {
                redsh[(g)     * 8 + q] = make_float2(a1p0, 0.f);
                redsh[(g + 8) * 8 + q] = make_float2(a1p1, 0.f);
            }
        }
        __syncthreads();   // (S1)
        if (tid < 16) {
            float a1 = 0.f;
#pragma unroll
            for (int qq = 0; qq < 8; qq++) a1 += redsh[tid * 8 + qq].x;
            lsesh[tid] = __logf(a1);     // logits small (|l|<~5): no max-shift needed
        }
        __syncthreads();   // (S2)

        float2 ls0[2], ls1[2];   // log-softmax(s): thread-local ownership
        {
            const float lse0 = lsesh[g];
            const float lse1 = lsesh[g + 8];
#pragma unroll
            for (int nt = 0; nt < 2; nt++) {
                ls0[nt] = make_float2(acc[nt][0] - lse0, acc[nt][1] - lse0);
                ls1[nt] = make_float2(acc[nt][2] - lse1, acc[nt][3] - lse1);
            }
        }

        // ---------------- teacher loop ---------------------------------------
#pragma unroll 1
        for (int t = 0; t < T_MODELS; t++) {
            float tacc[2][4];
#pragma unroll
            for (int nt = 0; nt < 2; nt++)
#pragma unroll
                for (int k = 0; k < 4; k++) tacc[nt][k] = 0.f;
            const uint32_t abase = bf_u32 + (uint32_t)t * (SUBTB * 2);
#pragma unroll
            for (int kk = 0; kk < 8; kk++) {
                uint32_t a[4];
                ldsm4(a, abase + kk * 32);
#pragma unroll
                for (int nt = 0; nt < 2; nt++)
                    mma16816(tacc[nt], a, wf1[nt][kk][0], wf1[nt][kk][1]);
            }
            float a1p0 = 0.f, a1p1 = 0.f, a2p0 = 0.f, a2p1 = 0.f;
#pragma unroll
            for (int nt = 0; nt < 2; nt++) {
                float v00 = tacc[nt][0] + b1r[nt].x, v01 = tacc[nt][1] + b1r[nt].y;
                float v10 = tacc[nt][2] + b1r[nt].x, v11 = tacc[nt][3] + b1r[nt].y;
                float e00 = __expf(v00), e01 = __expf(v01);
                float e10 = __expf(v10), e11 = __expf(v11);
                a1p0 += e00 + e01;  a1p1 += e10 + e11;
                a2p0 += e00 * (v00 - ls0[nt].x) + e01 * (v01 - ls0[nt].y);
                a2p1 += e10 * (v10 - ls1[nt].x) + e11 * (v11 - ls1[nt].y);
            }
            a1p0 += __shfl_xor_sync(0xffffffffu, a1p0, 1);
            a1p0 += __shfl_xor_sync(0xffffffffu, a1p0, 2);
            a1p1 += __shfl_xor_sync(0xffffffffu, a1p1, 1);
            a1p1 += __shfl_xor_sync(0xffffffffu, a1p1, 2);
            a2p0 += __shfl_xor_sync(0xffffffffu, a2p0, 1);
            a2p0 += __shfl_xor_sync(0xffffffffu, a2p0, 2);
            a2p1 += __shfl_xor_sync(0xffffffffu, a2p1, 1);
            a2p1 += __shfl_xor_sync(0xffffffffu, a2p1, 2);
            float2* rp = redsh + (t & 1) * 16 * 8;   // parity slab
            if (tc == 0) {
                rp[(g)     * 8 + q] = make_float2(a1p0, a2p0);
                rp[(g + 8) * 8 + q] = make_float2(a1p1, a2p1);
            }
            __syncthreads();   // (T_t)
            if (tid < 16) {
                const float2* rr = redsh + (t & 1) * 16 * 8 + tid * 8;
                float a1 = 0.f, a2 = 0.f;
#pragma unroll
                for (int qq = 0; qq < 8; qq++) { float2 v = rr[qq]; a1 += v.x; a2 += v.y; }
                klsh[t * 16 + tid] = a2 / a1 - __logf(a1);   // smem strip, not regs (dynamic t)
            }
        }

        // ---------------- teacher softmax + combine --------------------------
        if (tid < 16) {   // same lanes wrote klsh; same-thread smem st->ld is ordered
            const float sc = -0.08838834764831845f;   // -1/sqrt(128)
            float s[8]; float mx = -1e30f;
#pragma unroll
            for (int t = 0; t < 8; t++) { s[t] = klsh[t * 16 + tid] * sc; mx = fmaxf(mx, s[t]); }
            float sum = 0.f;
#pragma unroll
            for (int t = 0; t < 8; t++) { s[t] = __expf(s[t] - mx); sum += s[t]; }
            const float inv = 1.f / sum;
#pragma unroll
            for (int t = 0; t < 8; t++) wtsh[t * 16 + tid] = s[t] * inv;
        }
        __syncthreads();   // (W)

        {   // fp32 combine from the fp32 tiles (accuracy) -------------------
            const int r = tid >> 4;                 // 0..15
            const int cbase = (tid & 15) * 8;       // 8 cols per thread
            float w[8];
#pragma unroll
            for (int t = 0; t < 8; t++) w[t] = wtsh[t * 16 + r];
            float* orow = out + (node0 + r) * C_IN + cbase;
#pragma unroll
            for (int j = 0; j < 2; j++) {
                float4 a4 = make_float4(0.f, 0.f, 0.f, 0.f);
#pragma unroll
                for (int t = 0; t < 8; t++) {
                    float4 xv = *reinterpret_cast<const float4*>(buf + t * SUBT + r * XSTR + cbase + j * 4);
                    a4.x += w[t] * xv.x; a4.y += w[t] * xv.y;
                    a4.z += w[t] * xv.z; a4.w += w[t] * xv.w;
                }
                *reinterpret_cast<float4*>(orow + j * 4) = a4;
            }
        }

        cur = nxt;
        p ^= 1;
    }
}

extern "C" void kernel_launch(void* const* d_in, const int* in_sizes, int n_in,
                              void* d_out, int out_size) {
    (void)in_sizes; (void)n_in; (void)out_size;
    const float* s_out = (const float*)d_in[0];
    const float* t_out = (const float*)d_in[1];
    const float* w1w   = (const float*)d_in[2];
    const float* w1b   = (const float*)d_in[3];
    const float* w2w   = (const float*)d_in[4];
    const float* w2b   = (const float*)d_in[5];
    float* out = (float*)d_out;

    int dev = 0, nsm = 0;
    cudaGetDevice(&dev);
    cudaDeviceGetAttribute(&nsm, cudaDevAttrMultiProcessorCount, dev);
    if (nsm <= 0) nsm = 148;

    cudaFuncSetAttribute(fused_kd_attn, cudaFuncAttributeMaxDynamicSharedMemorySize, SMEM_TOTAL);
    fused_kd_attn<<<nsm, NTHREADS, SMEM_TOTAL>>>(s_out, t_out, w1w, w1b, w2w, w2b, out);
}